// round 1
// baseline (speedup 1.0000x reference)
#include <cuda_runtime.h>

#define F 128
#define N_MAX 100352
#define TNODES 8

// Scratch (device globals — allocation-free per harness rules)
__device__ float g_W[F * F];
__device__ float g_dinv[N_MAX];
__device__ float g_agg[(size_t)N_MAX * F];

// ---------------------------------------------------------------------------
// K1: evolve weight — one GRU step on W0 (batch = F rows).
// grid(F), block(3F). Block i computes row i of W.
// ---------------------------------------------------------------------------
__global__ void evolve_kernel(const float* __restrict__ W0,
                              const float* __restrict__ w_ih,
                              const float* __restrict__ w_hh,
                              const float* __restrict__ b_ih,
                              const float* __restrict__ b_hh) {
    __shared__ float s_row[F];
    __shared__ float s_gi[3 * F];
    __shared__ float s_gh[3 * F];
    int i = blockIdx.x;
    int j = threadIdx.x;  // 0..383
    if (j < F) s_row[j] = W0[i * F + j];
    __syncthreads();

    float gi = b_ih[j], gh = b_hh[j];
    const float* wi = w_ih + j * F;
    const float* wh = w_hh + j * F;
#pragma unroll 8
    for (int k = 0; k < F; k++) {
        float a = s_row[k];
        gi += a * wi[k];
        gh += a * wh[k];
    }
    s_gi[j] = gi;
    s_gh[j] = gh;
    __syncthreads();

    if (j < F) {
        float r = 1.f / (1.f + expf(-(s_gi[j] + s_gh[j])));
        float z = 1.f / (1.f + expf(-(s_gi[F + j] + s_gh[F + j])));
        float nn = tanhf(s_gi[2 * F + j] + r * s_gh[2 * F + j]);
        g_W[i * F + j] = (1.f - z) * nn + z * s_row[j];
    }
}

// ---------------------------------------------------------------------------
// K2-K4: degree accumulation -> dinv = rsqrt(deg). Self-loop gives deg init 1.
// ---------------------------------------------------------------------------
__global__ void deg_init(int n) {
    int i = blockIdx.x * blockDim.x + threadIdx.x;
    if (i < n) g_dinv[i] = 1.0f;
}

__global__ void deg_accum(const int* __restrict__ ei, const float* __restrict__ ew, int E) {
    int e = blockIdx.x * blockDim.x + threadIdx.x;
    if (e < E) atomicAdd(&g_dinv[ei[E + e]], ew[e]);
}

__global__ void deg_finish(int n) {
    int i = blockIdx.x * blockDim.x + threadIdx.x;
    if (i < n) g_dinv[i] = rsqrtf(g_dinv[i]);  // deg >= 1 always
}

// ---------------------------------------------------------------------------
// K5: agg[i,:] = dinv[i]^2 * x[i,:]   (self-loop contribution, norm = dinv_i^2)
// one thread per float4
// ---------------------------------------------------------------------------
__global__ void agg_init(const float* __restrict__ x, int n) {
    int idx = blockIdx.x * blockDim.x + threadIdx.x;  // over n*32 float4s
    if (idx >= n * 32) return;
    int row = idx >> 5;
    float d = g_dinv[row];
    float c = d * d;
    float4 v = ((const float4*)x)[idx];
    v.x *= c; v.y *= c; v.z *= c; v.w *= c;
    ((float4*)g_agg)[idx] = v;
}

// ---------------------------------------------------------------------------
// K6: edge scatter — warp per edge, coalesced 512B gather of x[row],
// vectorized red.global.add.v4.f32 into agg[col].
// ---------------------------------------------------------------------------
__global__ void scatter_kernel(const int* __restrict__ ei, const float* __restrict__ ew,
                               const float* __restrict__ x, int E) {
    int gw = (int)((blockIdx.x * (unsigned)blockDim.x + threadIdx.x) >> 5);
    int lane = threadIdx.x & 31;
    if (gw >= E) return;
    int r = __ldg(&ei[gw]);
    int c = __ldg(&ei[E + gw]);
    float coef = g_dinv[r] * __ldg(&ew[gw]) * g_dinv[c];
    float4 xv = ((const float4*)x)[r * 32 + lane];
    float* dst = g_agg + (size_t)c * F + lane * 4;
    asm volatile("red.global.add.v4.f32 [%0], {%1, %2, %3, %4};"
                 :: "l"(dst), "f"(xv.x * coef), "f"(xv.y * coef),
                    "f"(xv.z * coef), "f"(xv.w * coef)
                 : "memory");
}

// ---------------------------------------------------------------------------
// K7: fused out = relu(agg @ W) . lin_w + lin_b
// W + lin_w + per-warp agg staging in dynamic smem. 8 nodes per warp to
// amortize W smem reads. Each lane owns 4 output columns (lane*4..+3).
// ---------------------------------------------------------------------------
__global__ void final_kernel(const float* __restrict__ lin_w, const float* __restrict__ lin_b,
                             float* __restrict__ out, int n) {
    extern __shared__ float smem[];
    float* sW = smem;                 // F*F
    float* sLin = smem + F * F;       // F
    float* sAgg = sLin + F;           // 8 warps * TNODES * F

    int tid = threadIdx.x;  // 256
    for (int i = tid; i < F * F / 4; i += blockDim.x)
        ((float4*)sW)[i] = ((const float4*)g_W)[i];
    if (tid < F) sLin[tid] = lin_w[tid];
    __syncthreads();

    int warp = tid >> 5, lane = tid & 31;
    int node0 = (blockIdx.x * 8 + warp) * TNODES;
    float* sa = sAgg + warp * (TNODES * F);

#pragma unroll
    for (int nn = 0; nn < TNODES; nn++) {
        int node = node0 + nn;
        float4 v = make_float4(0.f, 0.f, 0.f, 0.f);
        if (node < n) v = ((const float4*)g_agg)[(size_t)node * 32 + lane];
        ((float4*)(sa + nn * F))[lane] = v;
    }
    __syncwarp();

    float acc[TNODES][4];
#pragma unroll
    for (int nn = 0; nn < TNODES; nn++)
        acc[nn][0] = acc[nn][1] = acc[nn][2] = acc[nn][3] = 0.f;

    int col = lane * 4;
    for (int k0 = 0; k0 < F; k0 += 4) {
        float4 w0 = *(const float4*)&sW[(k0 + 0) * F + col];
        float4 w1 = *(const float4*)&sW[(k0 + 1) * F + col];
        float4 w2 = *(const float4*)&sW[(k0 + 2) * F + col];
        float4 w3 = *(const float4*)&sW[(k0 + 3) * F + col];
#pragma unroll
        for (int nn = 0; nn < TNODES; nn++) {
            float4 a = *(const float4*)&sa[nn * F + k0];
            acc[nn][0] += a.x * w0.x + a.y * w1.x + a.z * w2.x + a.w * w3.x;
            acc[nn][1] += a.x * w0.y + a.y * w1.y + a.z * w2.y + a.w * w3.y;
            acc[nn][2] += a.x * w0.z + a.y * w1.z + a.z * w2.z + a.w * w3.z;
            acc[nn][3] += a.x * w0.w + a.y * w1.w + a.z * w2.w + a.w * w3.w;
        }
    }

    float lw0 = sLin[col], lw1 = sLin[col + 1], lw2 = sLin[col + 2], lw3 = sLin[col + 3];
    float bias = lin_b[0];
#pragma unroll
    for (int nn = 0; nn < TNODES; nn++) {
        float s = fmaxf(acc[nn][0], 0.f) * lw0 + fmaxf(acc[nn][1], 0.f) * lw1 +
                  fmaxf(acc[nn][2], 0.f) * lw2 + fmaxf(acc[nn][3], 0.f) * lw3;
#pragma unroll
        for (int off = 16; off; off >>= 1)
            s += __shfl_xor_sync(0xffffffffu, s, off);
        int node = node0 + nn;
        if (lane == 0 && node < n) out[node] = s + bias;
    }
}

// ---------------------------------------------------------------------------
extern "C" void kernel_launch(void* const* d_in, const int* in_sizes, int n_in,
                              void* d_out, int out_size) {
    const float* x     = (const float*)d_in[0];
    const int*   ei    = (const int*)d_in[1];
    const float* ew    = (const float*)d_in[2];
    const float* W0    = (const float*)d_in[3];
    const float* w_ih  = (const float*)d_in[4];
    const float* w_hh  = (const float*)d_in[5];
    const float* b_ih  = (const float*)d_in[6];
    const float* b_hh  = (const float*)d_in[7];
    const float* lin_w = (const float*)d_in[8];
    const float* lin_b = (const float*)d_in[9];
    float* out = (float*)d_out;

    int n = in_sizes[0] / F;
    int E = in_sizes[2];

    evolve_kernel<<<F, 3 * F>>>(W0, w_ih, w_hh, b_ih, b_hh);
    deg_init<<<(n + 255) / 256, 256>>>(n);
    deg_accum<<<(E + 255) / 256, 256>>>(ei, ew, E);
    deg_finish<<<(n + 255) / 256, 256>>>(n);
    agg_init<<<(n * 32 + 255) / 256, 256>>>(x, n);
    scatter_kernel<<<(E * 8 + 63) / 64 , 256>>>(ei, ew, x, E);  // warp per edge

    int warps = (n + TNODES - 1) / TNODES;
    int blocks = (warps + 7) / 8;
    size_t smem = (size_t)(F * F + F + 8 * TNODES * F) * sizeof(float);
    cudaFuncSetAttribute(final_kernel, cudaFuncAttributeMaxDynamicSharedMemorySize, (int)smem);
    final_kernel<<<blocks, 256, smem>>>(lin_w, lin_b, out, n);
}

// round 2
// speedup vs baseline: 1.0299x; 1.0299x over previous
#include <cuda_runtime.h>

#define F 128
#define N_MAX 100352
#define TNODES 8

// Scratch (device globals — allocation-free per harness rules)
__device__ float g_W[F * F];
__device__ float g_dinv[N_MAX];
__device__ float g_agg[(size_t)N_MAX * F];

// ---------------------------------------------------------------------------
// Packed fp32x2 helpers (sm_103a dual-lane fp32 pipe; full fp32 numerics)
// ---------------------------------------------------------------------------
__device__ __forceinline__ unsigned long long ffma2(unsigned long long a,
                                                    unsigned long long b,
                                                    unsigned long long c) {
    unsigned long long r;
    asm("fma.rn.f32x2 %0, %1, %2, %3;" : "=l"(r) : "l"(a), "l"(b), "l"(c));
    return r;
}
__device__ __forceinline__ unsigned long long pack2(float x) {
    unsigned long long r;
    asm("mov.b64 %0, {%1, %1};" : "=l"(r) : "f"(x));
    return r;
}
__device__ __forceinline__ float2 unpack2(unsigned long long v) {
    float2 f;
    asm("mov.b64 {%0, %1}, %2;" : "=f"(f.x), "=f"(f.y) : "l"(v));
    return f;
}

// ---------------------------------------------------------------------------
// K1: evolve weight — one GRU step on W0 (batch = F rows).
// grid(F), block(3F). Block i computes row i of W.
// ---------------------------------------------------------------------------
__global__ void evolve_kernel(const float* __restrict__ W0,
                              const float* __restrict__ w_ih,
                              const float* __restrict__ w_hh,
                              const float* __restrict__ b_ih,
                              const float* __restrict__ b_hh) {
    __shared__ float s_row[F];
    __shared__ float s_gi[3 * F];
    __shared__ float s_gh[3 * F];
    int i = blockIdx.x;
    int j = threadIdx.x;  // 0..383
    if (j < F) s_row[j] = W0[i * F + j];
    __syncthreads();

    float gi = b_ih[j], gh = b_hh[j];
    const float* wi = w_ih + j * F;
    const float* wh = w_hh + j * F;
#pragma unroll 8
    for (int k = 0; k < F; k++) {
        float a = s_row[k];
        gi += a * wi[k];
        gh += a * wh[k];
    }
    s_gi[j] = gi;
    s_gh[j] = gh;
    __syncthreads();

    if (j < F) {
        float r = 1.f / (1.f + expf(-(s_gi[j] + s_gh[j])));
        float z = 1.f / (1.f + expf(-(s_gi[F + j] + s_gh[F + j])));
        float nn = tanhf(s_gi[2 * F + j] + r * s_gh[2 * F + j]);
        g_W[i * F + j] = (1.f - z) * nn + z * s_row[j];
    }
}

// ---------------------------------------------------------------------------
// K2-K4: degree accumulation -> dinv = rsqrt(deg). Self-loop gives deg init 1.
// ---------------------------------------------------------------------------
__global__ void deg_init(int n) {
    int i = blockIdx.x * blockDim.x + threadIdx.x;
    if (i < n) g_dinv[i] = 1.0f;
}

__global__ void deg_accum(const int* __restrict__ ei, const float* __restrict__ ew, int E) {
    int e = blockIdx.x * blockDim.x + threadIdx.x;
    if (e < E) atomicAdd(&g_dinv[ei[E + e]], ew[e]);
}

__global__ void deg_finish(int n) {
    int i = blockIdx.x * blockDim.x + threadIdx.x;
    if (i < n) g_dinv[i] = rsqrtf(g_dinv[i]);  // deg >= 1 always
}

// ---------------------------------------------------------------------------
// K5: agg[i,:] = dinv[i]^2 * x[i,:]   (self-loop contribution, norm = dinv_i^2)
// one thread per float4
// ---------------------------------------------------------------------------
__global__ void agg_init(const float* __restrict__ x, int n) {
    int idx = blockIdx.x * blockDim.x + threadIdx.x;  // over n*32 float4s
    if (idx >= n * 32) return;
    int row = idx >> 5;
    float d = g_dinv[row];
    float c = d * d;
    float4 v = ((const float4*)x)[idx];
    v.x *= c; v.y *= c; v.z *= c; v.w *= c;
    ((float4*)g_agg)[idx] = v;
}

// ---------------------------------------------------------------------------
// K6: edge scatter — warp per edge, coalesced 512B gather of x[row],
// vectorized red.global.add.v4.f32 into agg[col].
// ---------------------------------------------------------------------------
__global__ void scatter_kernel(const int* __restrict__ ei, const float* __restrict__ ew,
                               const float* __restrict__ x, int E) {
    int gw = (int)((blockIdx.x * (unsigned)blockDim.x + threadIdx.x) >> 5);
    int lane = threadIdx.x & 31;
    if (gw >= E) return;
    int r = __ldg(&ei[gw]);
    int c = __ldg(&ei[E + gw]);
    float coef = g_dinv[r] * __ldg(&ew[gw]) * g_dinv[c];
    float4 xv = ((const float4*)x)[r * 32 + lane];
    float* dst = g_agg + (size_t)c * F + lane * 4;
    asm volatile("red.global.add.v4.f32 [%0], {%1, %2, %3, %4};"
                 :: "l"(dst), "f"(xv.x * coef), "f"(xv.y * coef),
                    "f"(xv.z * coef), "f"(xv.w * coef)
                 : "memory");
}

// ---------------------------------------------------------------------------
// K7: fused out = relu(agg @ W) . lin_w + lin_b   — packed f32x2 FMA version.
// W + lin_w + per-warp agg staging in dynamic smem. 8 nodes per warp.
// Each lane owns 4 output columns (lane*4..+3) = 2 f32x2 accumulators/node.
// ---------------------------------------------------------------------------
__global__ void final_kernel(const float* __restrict__ lin_w, const float* __restrict__ lin_b,
                             float* __restrict__ out, int n) {
    extern __shared__ float smem[];
    float* sW = smem;                 // F*F
    float* sLin = smem + F * F;       // F
    float* sAgg = sLin + F;           // 8 warps * TNODES * F

    int tid = threadIdx.x;  // 256
    for (int i = tid; i < F * F / 4; i += blockDim.x)
        ((float4*)sW)[i] = ((const float4*)g_W)[i];
    if (tid < F) sLin[tid] = lin_w[tid];
    __syncthreads();

    int warp = tid >> 5, lane = tid & 31;
    int node0 = (blockIdx.x * 8 + warp) * TNODES;
    float* sa = sAgg + warp * (TNODES * F);

#pragma unroll
    for (int nn = 0; nn < TNODES; nn++) {
        int node = node0 + nn;
        float4 v = make_float4(0.f, 0.f, 0.f, 0.f);
        if (node < n) v = ((const float4*)g_agg)[(size_t)node * 32 + lane];
        ((float4*)(sa + nn * F))[lane] = v;
    }
    __syncwarp();

    // acc[nn][0] = cols (col, col+1), acc[nn][1] = cols (col+2, col+3)
    unsigned long long acc[TNODES][2];
#pragma unroll
    for (int nn = 0; nn < TNODES; nn++) { acc[nn][0] = 0ULL; acc[nn][1] = 0ULL; }

    int col = lane * 4;
    for (int k0 = 0; k0 < F; k0 += 4) {
        // each w row slice: 4 floats = 2 packed f32x2 (bitwise reinterpret)
        ulonglong2 w0 = *(const ulonglong2*)&sW[(k0 + 0) * F + col];
        ulonglong2 w1 = *(const ulonglong2*)&sW[(k0 + 1) * F + col];
        ulonglong2 w2 = *(const ulonglong2*)&sW[(k0 + 2) * F + col];
        ulonglong2 w3 = *(const ulonglong2*)&sW[(k0 + 3) * F + col];
#pragma unroll
        for (int nn = 0; nn < TNODES; nn++) {
            float4 a = *(const float4*)&sa[nn * F + k0];
            unsigned long long ax = pack2(a.x), ay = pack2(a.y),
                               az = pack2(a.z), aw = pack2(a.w);
            acc[nn][0] = ffma2(ax, w0.x, acc[nn][0]);
            acc[nn][0] = ffma2(ay, w1.x, acc[nn][0]);
            acc[nn][0] = ffma2(az, w2.x, acc[nn][0]);
            acc[nn][0] = ffma2(aw, w3.x, acc[nn][0]);
            acc[nn][1] = ffma2(ax, w0.y, acc[nn][1]);
            acc[nn][1] = ffma2(ay, w1.y, acc[nn][1]);
            acc[nn][1] = ffma2(az, w2.y, acc[nn][1]);
            acc[nn][1] = ffma2(aw, w3.y, acc[nn][1]);
        }
    }

    float lw0 = sLin[col], lw1 = sLin[col + 1], lw2 = sLin[col + 2], lw3 = sLin[col + 3];
    float bias = lin_b[0];
#pragma unroll
    for (int nn = 0; nn < TNODES; nn++) {
        float2 h01 = unpack2(acc[nn][0]);
        float2 h23 = unpack2(acc[nn][1]);
        float s = fmaxf(h01.x, 0.f) * lw0 + fmaxf(h01.y, 0.f) * lw1 +
                  fmaxf(h23.x, 0.f) * lw2 + fmaxf(h23.y, 0.f) * lw3;
#pragma unroll
        for (int off = 16; off; off >>= 1)
            s += __shfl_xor_sync(0xffffffffu, s, off);
        int node = node0 + nn;
        if (lane == 0 && node < n) out[node] = s + bias;
    }
}

// ---------------------------------------------------------------------------
extern "C" void kernel_launch(void* const* d_in, const int* in_sizes, int n_in,
                              void* d_out, int out_size) {
    const float* x     = (const float*)d_in[0];
    const int*   ei    = (const int*)d_in[1];
    const float* ew    = (const float*)d_in[2];
    const float* W0    = (const float*)d_in[3];
    const float* w_ih  = (const float*)d_in[4];
    const float* w_hh  = (const float*)d_in[5];
    const float* b_ih  = (const float*)d_in[6];
    const float* b_hh  = (const float*)d_in[7];
    const float* lin_w = (const float*)d_in[8];
    const float* lin_b = (const float*)d_in[9];
    float* out = (float*)d_out;

    int n = in_sizes[0] / F;
    int E = in_sizes[2];

    evolve_kernel<<<F, 3 * F>>>(W0, w_ih, w_hh, b_ih, b_hh);
    deg_init<<<(n + 255) / 256, 256>>>(n);
    deg_accum<<<(E + 255) / 256, 256>>>(ei, ew, E);
    deg_finish<<<(n + 255) / 256, 256>>>(n);
    agg_init<<<(n * 32 + 255) / 256, 256>>>(x, n);
    scatter_kernel<<<(E * 8 + 63) / 64 , 256>>>(ei, ew, x, E);  // warp per edge

    int warps = (n + TNODES - 1) / TNODES;
    int blocks = (warps + 7) / 8;
    size_t smem = (size_t)(F * F + F + 8 * TNODES * F) * sizeof(float);
    cudaFuncSetAttribute(final_kernel, cudaFuncAttributeMaxDynamicSharedMemorySize, (int)smem);
    final_kernel<<<blocks, 256, smem>>>(lin_w, lin_b, out, n);
}

// round 4
// speedup vs baseline: 1.3352x; 1.2964x over previous
#include <cuda_runtime.h>

#define F 128
#define N_MAX 100352
#define E_MAX 1600000

// Scratch (device globals — allocation-free per harness rules)
__device__ float g_W[F * F];
__device__ float g_dinv[N_MAX];
__device__ int   g_count[N_MAX];
__device__ int   g_offset[N_MAX];
__device__ int   g_cursor[N_MAX];
__device__ int   g_bsum[(N_MAX + 255) / 256];
__device__ int   g_srow[E_MAX];
__device__ float g_scoef[E_MAX];
__device__ float g_agg[(size_t)N_MAX * F];

// ---------------------------------------------------------------------------
// Packed fp32x2 helpers (sm_103a dual-lane fp32 pipe; full fp32 numerics)
// ---------------------------------------------------------------------------
__device__ __forceinline__ unsigned long long ffma2(unsigned long long a,
                                                    unsigned long long b,
                                                    unsigned long long c) {
    unsigned long long r;
    asm("fma.rn.f32x2 %0, %1, %2, %3;" : "=l"(r) : "l"(a), "l"(b), "l"(c));
    return r;
}
__device__ __forceinline__ unsigned long long pack2(float x) {
    unsigned long long r;
    asm("mov.b64 %0, {%1, %1};" : "=l"(r) : "f"(x));
    return r;
}
__device__ __forceinline__ float2 unpack2(unsigned long long v) {
    float2 f;
    asm("mov.b64 {%0, %1}, %2;" : "=f"(f.x), "=f"(f.y) : "l"(v));
    return f;
}

// ---------------------------------------------------------------------------
// K1: evolve weight — one GRU step on W0 (batch = F rows).
// ---------------------------------------------------------------------------
__global__ void evolve_kernel(const float* __restrict__ W0,
                              const float* __restrict__ w_ih,
                              const float* __restrict__ w_hh,
                              const float* __restrict__ b_ih,
                              const float* __restrict__ b_hh) {
    __shared__ float s_row[F];
    __shared__ float s_gi[3 * F];
    __shared__ float s_gh[3 * F];
    int i = blockIdx.x;
    int j = threadIdx.x;  // 0..383
    if (j < F) s_row[j] = W0[i * F + j];
    __syncthreads();

    float gi = b_ih[j], gh = b_hh[j];
    const float* wi = w_ih + j * F;
    const float* wh = w_hh + j * F;
#pragma unroll 8
    for (int k = 0; k < F; k++) {
        float a = s_row[k];
        gi += a * wi[k];
        gh += a * wh[k];
    }
    s_gi[j] = gi;
    s_gh[j] = gh;
    __syncthreads();

    if (j < F) {
        float r = 1.f / (1.f + expf(-(s_gi[j] + s_gh[j])));
        float z = 1.f / (1.f + expf(-(s_gi[F + j] + s_gh[F + j])));
        float nn = tanhf(s_gi[2 * F + j] + r * s_gh[2 * F + j]);
        g_W[i * F + j] = (1.f - z) * nn + z * s_row[j];
    }
}

// ---------------------------------------------------------------------------
// K2: init deg (self loop weight 1) and histogram counters
// ---------------------------------------------------------------------------
__global__ void init_kernel(int n) {
    int i = blockIdx.x * blockDim.x + threadIdx.x;
    if (i < n) { g_dinv[i] = 1.0f; g_count[i] = 0; }
}

// K3: degree accumulation + target histogram in one pass
__global__ void deg_hist(const int* __restrict__ ei, const float* __restrict__ ew, int E) {
    int e = blockIdx.x * blockDim.x + threadIdx.x;
    if (e < E) {
        int c = ei[E + e];
        atomicAdd(&g_dinv[c], ew[e]);
        atomicAdd(&g_count[c], 1);
    }
}

// K4: dinv = rsqrt(deg)
__global__ void deg_finish(int n) {
    int i = blockIdx.x * blockDim.x + threadIdx.x;
    if (i < n) g_dinv[i] = rsqrtf(g_dinv[i]);  // deg >= 1 always
}

// ---------------------------------------------------------------------------
// K5-K7: exclusive scan of g_count -> g_offset (and g_cursor copy)
// ---------------------------------------------------------------------------
__global__ void scan_part(int n) {
    __shared__ int s[256];
    int i = blockIdx.x * 256 + threadIdx.x;
    s[threadIdx.x] = (i < n) ? g_count[i] : 0;
    __syncthreads();
    for (int st = 128; st; st >>= 1) {
        if (threadIdx.x < st) s[threadIdx.x] += s[threadIdx.x + st];
        __syncthreads();
    }
    if (threadIdx.x == 0) g_bsum[blockIdx.x] = s[0];
}

__global__ void scan_top(int nb) {
    if (threadIdx.x == 0) {
        int run = 0;
        for (int b = 0; b < nb; b++) {
            int v = g_bsum[b];
            g_bsum[b] = run;
            run += v;
        }
    }
}

__global__ void scan_final(int n) {
    __shared__ int s[257];
    int i = blockIdx.x * 256 + threadIdx.x;
    int v = (i < n) ? g_count[i] : 0;
    s[threadIdx.x + 1] = v;
    if (threadIdx.x == 0) s[0] = 0;
    __syncthreads();
    // Hillis-Steele inclusive scan on shifted array -> exclusive prefix at s[tid]
    for (int st = 1; st < 256; st <<= 1) {
        int add = (threadIdx.x >= st) ? s[threadIdx.x - st] : 0;  // FIXED
        __syncthreads();
        s[threadIdx.x] += add;
        __syncthreads();
    }
    if (i < n) {
        int off = g_bsum[blockIdx.x] + s[threadIdx.x];
        g_offset[i] = off;
        g_cursor[i] = off;
    }
}

// ---------------------------------------------------------------------------
// K8: place edges into target-sorted order with precomputed coefficients
// ---------------------------------------------------------------------------
__global__ void place_kernel(const int* __restrict__ ei, const float* __restrict__ ew, int E) {
    int e = blockIdx.x * blockDim.x + threadIdx.x;
    if (e >= E) return;
    int r = ei[e];
    int c = ei[E + e];
    int p = atomicAdd(&g_cursor[c], 1);
    g_srow[p] = r;
    g_scoef[p] = g_dinv[r] * ew[e] * g_dinv[c];
}

// ---------------------------------------------------------------------------
// K9: aggregate — warp per node. Lanes batch-load up to 32 edge records,
// shuffle-broadcast, gather x rows (float4/lane), accumulate in registers.
// Self-loop (dinv_c^2 * x[c]) folded in. One plain 16B store per lane.
// ---------------------------------------------------------------------------
__global__ void agg_kernel(const float* __restrict__ x, int n) {
    int gw = (int)((blockIdx.x * (unsigned)blockDim.x + threadIdx.x) >> 5);
    int lane = threadIdx.x & 31;
    if (gw >= n) return;

    int off = g_offset[gw];
    int cnt = g_count[gw];
    float dc = g_dinv[gw];
    float sc = dc * dc;

    float4 acc = ((const float4*)x)[(size_t)gw * 32 + lane];
    acc.x *= sc; acc.y *= sc; acc.z *= sc; acc.w *= sc;

    for (int base = 0; base < cnt; base += 32) {
        int m = min(32, cnt - base);
        int r_l = 0; float cf_l = 0.f;
        if (lane < m) {
            r_l = __ldg(&g_srow[off + base + lane]);
            cf_l = __ldg(&g_scoef[off + base + lane]);
        }
        for (int j = 0; j < m; j++) {
            int r = __shfl_sync(0xffffffffu, r_l, j);
            float cf = __shfl_sync(0xffffffffu, cf_l, j);
            float4 xv = ((const float4*)x)[(size_t)r * 32 + lane];
            acc.x += cf * xv.x;
            acc.y += cf * xv.y;
            acc.z += cf * xv.z;
            acc.w += cf * xv.w;
        }
    }
    ((float4*)g_agg)[(size_t)gw * 32 + lane] = acc;
}

// ---------------------------------------------------------------------------
// K10: fused out = relu(agg @ W) . lin_w + lin_b — packed f32x2 FMA.
// ---------------------------------------------------------------------------
#define TNODES 8
__global__ void final_kernel(const float* __restrict__ lin_w, const float* __restrict__ lin_b,
                             float* __restrict__ out, int n) {
    extern __shared__ float smem[];
    float* sW = smem;                 // F*F
    float* sLin = smem + F * F;       // F
    float* sAgg = sLin + F;           // 8 warps * TNODES * F

    int tid = threadIdx.x;  // 256
    for (int i = tid; i < F * F / 4; i += blockDim.x)
        ((float4*)sW)[i] = ((const float4*)g_W)[i];
    if (tid < F) sLin[tid] = lin_w[tid];
    __syncthreads();

    int warp = tid >> 5, lane = tid & 31;
    int node0 = (blockIdx.x * 8 + warp) * TNODES;
    float* sa = sAgg + warp * (TNODES * F);

#pragma unroll
    for (int nn = 0; nn < TNODES; nn++) {
        int node = node0 + nn;
        float4 v = make_float4(0.f, 0.f, 0.f, 0.f);
        if (node < n) v = ((const float4*)g_agg)[(size_t)node * 32 + lane];
        ((float4*)(sa + nn * F))[lane] = v;
    }
    __syncwarp();

    unsigned long long acc[TNODES][2];
#pragma unroll
    for (int nn = 0; nn < TNODES; nn++) { acc[nn][0] = 0ULL; acc[nn][1] = 0ULL; }

    int col = lane * 4;
    for (int k0 = 0; k0 < F; k0 += 4) {
        ulonglong2 w0 = *(const ulonglong2*)&sW[(k0 + 0) * F + col];
        ulonglong2 w1 = *(const ulonglong2*)&sW[(k0 + 1) * F + col];
        ulonglong2 w2 = *(const ulonglong2*)&sW[(k0 + 2) * F + col];
        ulonglong2 w3 = *(const ulonglong2*)&sW[(k0 + 3) * F + col];
#pragma unroll
        for (int nn = 0; nn < TNODES; nn++) {
            float4 a = *(const float4*)&sa[nn * F + k0];
            unsigned long long ax = pack2(a.x), ay = pack2(a.y),
                               az = pack2(a.z), aw = pack2(a.w);
            acc[nn][0] = ffma2(ax, w0.x, acc[nn][0]);
            acc[nn][0] = ffma2(ay, w1.x, acc[nn][0]);
            acc[nn][0] = ffma2(az, w2.x, acc[nn][0]);
            acc[nn][0] = ffma2(aw, w3.x, acc[nn][0]);
            acc[nn][1] = ffma2(ax, w0.y, acc[nn][1]);
            acc[nn][1] = ffma2(ay, w1.y, acc[nn][1]);
            acc[nn][1] = ffma2(az, w2.y, acc[nn][1]);
            acc[nn][1] = ffma2(aw, w3.y, acc[nn][1]);
        }
    }

    float lw0 = sLin[col], lw1 = sLin[col + 1], lw2 = sLin[col + 2], lw3 = sLin[col + 3];
    float bias = lin_b[0];
#pragma unroll
    for (int nn = 0; nn < TNODES; nn++) {
        float2 h01 = unpack2(acc[nn][0]);
        float2 h23 = unpack2(acc[nn][1]);
        float s = fmaxf(h01.x, 0.f) * lw0 + fmaxf(h01.y, 0.f) * lw1 +
                  fmaxf(h23.x, 0.f) * lw2 + fmaxf(h23.y, 0.f) * lw3;
#pragma unroll
        for (int off = 16; off; off >>= 1)
            s += __shfl_xor_sync(0xffffffffu, s, off);
        int node = node0 + nn;
        if (lane == 0 && node < n) out[node] = s + bias;
    }
}

// ---------------------------------------------------------------------------
extern "C" void kernel_launch(void* const* d_in, const int* in_sizes, int n_in,
                              void* d_out, int out_size) {
    const float* x     = (const float*)d_in[0];
    const int*   ei    = (const int*)d_in[1];
    const float* ew    = (const float*)d_in[2];
    const float* W0    = (const float*)d_in[3];
    const float* w_ih  = (const float*)d_in[4];
    const float* w_hh  = (const float*)d_in[5];
    const float* b_ih  = (const float*)d_in[6];
    const float* b_hh  = (const float*)d_in[7];
    const float* lin_w = (const float*)d_in[8];
    const float* lin_b = (const float*)d_in[9];
    float* out = (float*)d_out;

    int n = in_sizes[0] / F;
    int E = in_sizes[2];
    int nb = (n + 255) / 256;

    evolve_kernel<<<F, 3 * F>>>(W0, w_ih, w_hh, b_ih, b_hh);
    init_kernel<<<nb, 256>>>(n);
    deg_hist<<<(E + 255) / 256, 256>>>(ei, ew, E);
    deg_finish<<<nb, 256>>>(n);
    scan_part<<<nb, 256>>>(n);
    scan_top<<<1, 32>>>(nb);
    scan_final<<<nb, 256>>>(n);
    place_kernel<<<(E + 255) / 256, 256>>>(ei, ew, E);
    agg_kernel<<<(n * 32 + 255) / 256, 256>>>(x, n);  // warp per node

    int warps = (n + TNODES - 1) / TNODES;
    int blocks = (warps + 7) / 8;
    size_t smem = (size_t)(F * F + F + 8 * TNODES * F) * sizeof(float);
    cudaFuncSetAttribute(final_kernel, cudaFuncAttributeMaxDynamicSharedMemorySize, (int)smem);
    final_kernel<<<blocks, 256, smem>>>(lin_w, lin_b, out, n);
}